// round 1
// baseline (speedup 1.0000x reference)
#include <cuda_runtime.h>
#include <cuda_bf16.h>
#include <math.h>

// ---------------- problem constants ----------------
#define DIMC   96
#define HEADS  6
#define HD     16            // head dim
#define WS     8
#define OWS    12
#define PADW   2
#define DSP    24            // D = H = W = 24
#define NTOK   (24*24*24)    // 13824
#define NWIN   27            // 3x3x3 windows
#define QW3    512           // WS^3
#define KW3    1728          // OWS^3
#define MLPH   192
#define TBL    6859          // 19^3

typedef unsigned long long ull;

// ---------------- scratch (static device globals; no allocation) ----------------
__device__ __align__(256) float g_xn  [NTOK * DIMC];
__device__ __align__(256) float g_qkv [NTOK * 3 * DIMC];
__device__ __align__(256) float g_bias[(size_t)HEADS * KW3 * QW3];   // [h][k][q]
__device__ __align__(256) float g_attn[NTOK * DIMC];
__device__ __align__(256) float g_x2  [NTOK * DIMC];
__device__ __align__(256) float g_x2n [NTOK * DIMC];
__device__ __align__(256) float g_h1  [NTOK * MLPH];

// ---------------- f32x2 packed helpers (sm_103a) ----------------
__device__ __forceinline__ ull pk2(float lo, float hi) {
    ull r; asm("mov.b64 %0, {%1, %2};" : "=l"(r) : "f"(lo), "f"(hi)); return r;
}
__device__ __forceinline__ void upk2(ull p, float& lo, float& hi) {
    asm("mov.b64 {%0, %1}, %2;" : "=f"(lo), "=f"(hi) : "l"(p));
}
__device__ __forceinline__ ull fma2(ull a, ull b, ull c) {
    ull d; asm("fma.rn.f32x2 %0, %1, %2, %3;" : "=l"(d) : "l"(a), "l"(b), "l"(c)); return d;
}
__device__ __forceinline__ ull mul2(ull a, ull b) {
    ull d; asm("mul.rn.f32x2 %0, %1, %2;" : "=l"(d) : "l"(a), "l"(b)); return d;
}

// ---------------- LayerNorm: one warp per token (96 = 3*32) ----------------
__global__ void ln_kernel(const float* __restrict__ in,
                          const float* __restrict__ g,
                          const float* __restrict__ b,
                          float* __restrict__ out) {
    int t    = blockIdx.x * 8 + (threadIdx.x >> 5);
    int lane = threadIdx.x & 31;
    const float* row = in + (size_t)t * DIMC;
    float v0 = row[lane], v1 = row[lane + 32], v2 = row[lane + 64];
    float s  = v0 + v1 + v2;
    float sq = v0 * v0 + v1 * v1 + v2 * v2;
    #pragma unroll
    for (int o = 16; o; o >>= 1) {
        s  += __shfl_xor_sync(0xffffffffu, s,  o);
        sq += __shfl_xor_sync(0xffffffffu, sq, o);
    }
    float mean = s * (1.0f / DIMC);
    float var  = sq * (1.0f / DIMC) - mean * mean;
    float r    = rsqrtf(var + 1e-5f);
    float* orow = out + (size_t)t * DIMC;
    orow[lane]      = (v0 - mean) * r * g[lane]      + b[lane];
    orow[lane + 32] = (v1 - mean) * r * g[lane + 32] + b[lane + 32];
    orow[lane + 64] = (v2 - mean) * r * g[lane + 64] + b[lane + 64];
}

// ---------------- token GEMM: out[t][o] = sum_c in[t][c]*w[o][c] (+b, +res / gelu) ----------------
// TM tokens per block, COUT threads. Activations staged transposed in SMEM -> LDS.128 broadcast.
template <int CIN, int COUT, int TM, int MODE>  // MODE: 0=+b, 1=+b+res, 2=gelu(+b)
__global__ void tok_gemm(const float* __restrict__ in,
                         const float* __restrict__ w,
                         const float* __restrict__ bias,
                         const float* __restrict__ res,
                         float* __restrict__ out) {
    __shared__ __align__(16) float xs[CIN * TM];   // [c][t]
    int t0 = blockIdx.x * TM;
    for (int i = threadIdx.x; i < TM * CIN; i += COUT) {
        int t = i / CIN, c = i - t * CIN;
        xs[c * TM + t] = in[(size_t)t0 * CIN + i];
    }
    __syncthreads();
    int o = threadIdx.x;
    float acc[TM];
    #pragma unroll
    for (int t = 0; t < TM; t++) acc[t] = 0.0f;
    const float* wrow = w + (size_t)o * CIN;
    #pragma unroll 4
    for (int c = 0; c < CIN; c++) {
        float wv = wrow[c];
        const float4* xp = (const float4*)(xs + c * TM);
        float4 a0 = xp[0], a1 = xp[1], a2 = xp[2], a3 = xp[3];
        acc[0]  += a0.x * wv;  acc[1]  += a0.y * wv;  acc[2]  += a0.z * wv;  acc[3]  += a0.w * wv;
        acc[4]  += a1.x * wv;  acc[5]  += a1.y * wv;  acc[6]  += a1.z * wv;  acc[7]  += a1.w * wv;
        acc[8]  += a2.x * wv;  acc[9]  += a2.y * wv;  acc[10] += a2.z * wv;  acc[11] += a2.w * wv;
        acc[12] += a3.x * wv;  acc[13] += a3.y * wv;  acc[14] += a3.z * wv;  acc[15] += a3.w * wv;
    }
    float bo = bias[o];
    #pragma unroll
    for (int t = 0; t < TM; t++) {
        float v = acc[t] + bo;
        if (MODE == 1) v += res[(size_t)(t0 + t) * COUT + o];
        if (MODE == 2) v = 0.5f * v * (1.0f + erff(v * 0.70710678118654752f));
        out[(size_t)(t0 + t) * COUT + o] = v;
    }
}

// ---------------- bias precompute: g_bias[h][k][q] = rpb[rpi[q][k]][h] ----------------
__global__ void bias_kernel(const int* __restrict__ rpi, const float* __restrict__ rpb) {
    int i = blockIdx.x * 256 + threadIdx.x;        // i = k*512 + q
    if (i >= KW3 * QW3) return;
    int k = i >> 9, q = i & 511;
    int idx = rpi[q * KW3 + k];
    #pragma unroll
    for (int h = 0; h < HEADS; h++)
        g_bias[((size_t)h * KW3 + k) * QW3 + q] = rpb[idx * HEADS + h];
}

// ---------------- attention: one block = (window, head, 128-query chunk) ----------------
__global__ void __launch_bounds__(128) attn_kernel() {
    __shared__ float4 ks4[64 * 4];
    __shared__ float4 vs4[64 * 4];

    int b   = blockIdx.x;
    int w   = b / 24;  int rem = b - w * 24;
    int h   = rem >> 2, qc = rem & 3;
    int wd  = w / 9;   int wr = w - wd * 9;
    int wh  = wr / 3;  int ww = wr - wh * 3;
    int tid = threadIdx.x;

    int qw = (qc << 7) + tid;                       // query index within window [0,512)
    int z  = qw >> 6, y = (qw >> 3) & 7, xx = qw & 7;
    int tq = ((wd * 8 + z) * DSP + (wh * 8 + y)) * DSP + (ww * 8 + xx);

    // q, pre-scaled, packed as 8 f32x2 pairs
    const float4* qp4 = (const float4*)(g_qkv + (size_t)tq * 288 + h * HD);
    ull qp[8];
    #pragma unroll
    for (int i = 0; i < 4; i++) {
        float4 v = qp4[i];
        qp[2 * i]     = pk2(v.x * 0.25f, v.y * 0.25f);
        qp[2 * i + 1] = pk2(v.z * 0.25f, v.w * 0.25f);
    }

    ull accp[8];
    #pragma unroll
    for (int c = 0; c < 8; c++) accp[c] = 0ull;
    float m = -3.0e38f, l = 0.0f;

    const float* brow = g_bias + ((size_t)h * KW3) * QW3 + qw;

    int j = tid & 63;                                // key slot this thread loads
    #pragma unroll 1
    for (int kt = 0; kt < 27; kt++) {
        __syncthreads();
        {   // cooperative gather of K (threads 0-63) / V (threads 64-127), zero-padded
            int kk = kt * 64 + j;
            int kz = kk / 144; int r2 = kk - kz * 144;
            int ky = r2 / 12;  int kx = r2 - ky * 12;
            int gz = wd * 8 + kz - PADW, gy = wh * 8 + ky - PADW, gx = ww * 8 + kx - PADW;
            float4* dst = (tid < 64 ? ks4 : vs4) + j * 4;
            if ((unsigned)gz < 24u && (unsigned)gy < 24u && (unsigned)gx < 24u) {
                const float4* src = (const float4*)(g_qkv +
                    (size_t)((gz * DSP + gy) * DSP + gx) * 288 + (tid < 64 ? 96 : 192) + h * HD);
                dst[0] = src[0]; dst[1] = src[1]; dst[2] = src[2]; dst[3] = src[3];
            } else {
                float4 zz = make_float4(0.f, 0.f, 0.f, 0.f);
                dst[0] = zz; dst[1] = zz; dst[2] = zz; dst[3] = zz;
            }
        }
        __syncthreads();

        const float* bk = brow + (size_t)kt * 64 * QW3;
        #pragma unroll 1
        for (int chunk = 0; chunk < 4; chunk++) {
            float lg[16]; float cm = -3.0e38f;
            #pragma unroll
            for (int i = 0; i < 16; i++) {
                int jj = (chunk << 4) + i;
                const float4* kf = ks4 + jj * 4;
                float4 k0 = kf[0], k1 = kf[1], k2 = kf[2], k3 = kf[3];
                ull sp = mul2(qp[0], pk2(k0.x, k0.y));
                sp = fma2(qp[1], pk2(k0.z, k0.w), sp);
                sp = fma2(qp[2], pk2(k1.x, k1.y), sp);
                sp = fma2(qp[3], pk2(k1.z, k1.w), sp);
                sp = fma2(qp[4], pk2(k2.x, k2.y), sp);
                sp = fma2(qp[5], pk2(k2.z, k2.w), sp);
                sp = fma2(qp[6], pk2(k3.x, k3.y), sp);
                sp = fma2(qp[7], pk2(k3.z, k3.w), sp);
                float slo, shi; upk2(sp, slo, shi);
                float s = slo + shi + __ldg(bk + (size_t)jj * QW3);
                lg[i] = s; cm = fmaxf(cm, s);
            }
            if (cm > m) {                            // one rescale per 16-key chunk max
                float f = __expf(m - cm);
                ull fp = pk2(f, f);
                l *= f;
                #pragma unroll
                for (int c = 0; c < 8; c++) accp[c] = mul2(accp[c], fp);
                m = cm;
            }
            #pragma unroll
            for (int i = 0; i < 16; i++) {
                float p = __expf(lg[i] - m); l += p;
                ull pp = pk2(p, p);
                const float4* vf = vs4 + ((chunk << 4) + i) * 4;
                float4 v0 = vf[0], v1 = vf[1], v2 = vf[2], v3 = vf[3];
                accp[0] = fma2(pp, pk2(v0.x, v0.y), accp[0]);
                accp[1] = fma2(pp, pk2(v0.z, v0.w), accp[1]);
                accp[2] = fma2(pp, pk2(v1.x, v1.y), accp[2]);
                accp[3] = fma2(pp, pk2(v1.z, v1.w), accp[3]);
                accp[4] = fma2(pp, pk2(v2.x, v2.y), accp[4]);
                accp[5] = fma2(pp, pk2(v2.z, v2.w), accp[5]);
                accp[6] = fma2(pp, pk2(v3.x, v3.y), accp[6]);
                accp[7] = fma2(pp, pk2(v3.z, v3.w), accp[7]);
            }
        }
    }

    float inv = 1.0f / l;
    float ov[16];
    #pragma unroll
    for (int c = 0; c < 8; c++) {
        float lo, hi; upk2(accp[c], lo, hi);
        ov[2 * c] = lo * inv; ov[2 * c + 1] = hi * inv;
    }
    float4* op = (float4*)(g_attn + (size_t)tq * DIMC + h * HD);
    op[0] = make_float4(ov[0],  ov[1],  ov[2],  ov[3]);
    op[1] = make_float4(ov[4],  ov[5],  ov[6],  ov[7]);
    op[2] = make_float4(ov[8],  ov[9],  ov[10], ov[11]);
    op[3] = make_float4(ov[12], ov[13], ov[14], ov[15]);
}

// ---------------- launch ----------------
extern "C" void kernel_launch(void* const* d_in, const int* in_sizes, int n_in,
                              void* d_out, int out_size) {
    const float* x      = (const float*)d_in[0];
    const float* ln1_w  = (const float*)d_in[1];
    const float* ln1_b  = (const float*)d_in[2];
    const float* qkv_w  = (const float*)d_in[3];
    const float* qkv_b  = (const float*)d_in[4];
    const float* rpb    = (const float*)d_in[5];
    const float* proj_w = (const float*)d_in[6];
    const float* proj_b = (const float*)d_in[7];
    const float* ln2_w  = (const float*)d_in[8];
    const float* ln2_b  = (const float*)d_in[9];
    const float* fc1_w  = (const float*)d_in[10];
    const float* fc1_b  = (const float*)d_in[11];
    const float* fc2_w  = (const float*)d_in[12];
    const float* fc2_b  = (const float*)d_in[13];
    const int*   rpi    = (const int*)  d_in[14];
    float* out = (float*)d_out;

    float* xn   = nullptr; cudaGetSymbolAddress((void**)&xn,   g_xn);
    float* qkv  = nullptr; cudaGetSymbolAddress((void**)&qkv,  g_qkv);
    float* attn = nullptr; cudaGetSymbolAddress((void**)&attn, g_attn);
    float* x2   = nullptr; cudaGetSymbolAddress((void**)&x2,   g_x2);
    float* x2n  = nullptr; cudaGetSymbolAddress((void**)&x2n,  g_x2n);
    float* h1   = nullptr; cudaGetSymbolAddress((void**)&h1,   g_h1);

    // bias gather is independent of the LN/QKV chain
    bias_kernel<<<(KW3 * QW3 + 255) / 256, 256>>>(rpi, rpb);

    ln_kernel<<<NTOK / 8, 256>>>(x, ln1_w, ln1_b, xn);
    tok_gemm<96, 288, 16, 0><<<NTOK / 16, 288>>>(xn, qkv_w, qkv_b, nullptr, qkv);

    attn_kernel<<<NWIN * HEADS * 4, 128>>>();

    tok_gemm<96, 96, 16, 1><<<NTOK / 16, 96>>>(attn, proj_w, proj_b, x, x2);
    ln_kernel<<<NTOK / 8, 256>>>(x2, ln2_w, ln2_b, x2n);
    tok_gemm<96, 192, 16, 2><<<NTOK / 16, 192>>>(x2n, fc1_w, fc1_b, nullptr, h1);
    tok_gemm<192, 96, 16, 1><<<NTOK / 16, 96>>>(h1, fc2_w, fc2_b, x2, out);
}

// round 2
// speedup vs baseline: 1.3880x; 1.3880x over previous
#include <cuda_runtime.h>
#include <cuda_bf16.h>
#include <math.h>

// ---------------- problem constants ----------------
#define DIMC   96
#define HEADS  6
#define HD     16
#define WS     8
#define OWS    12
#define PADW   2
#define DSP    24
#define NTOK   (24*24*24)
#define NWIN   27
#define QW3    512
#define KW3    1728
#define MLPH   192
#define NSPLIT 3
#define NBLK   (NWIN*HEADS*4)     // 648 attention (w,h,qc) blocks

typedef unsigned long long ull;

// ---------------- scratch ----------------
__device__ __align__(256) float g_xn  [NTOK * DIMC];
__device__ __align__(256) float g_qkv [NTOK * 3 * DIMC];
__device__ __align__(256) float g_bias[(size_t)HEADS * KW3 * QW3];   // [h][k][q]
__device__ __align__(256) float g_attn[NTOK * DIMC];
__device__ __align__(256) float g_x2  [NTOK * DIMC];
__device__ __align__(256) float g_x2n [NTOK * DIMC];
__device__ __align__(256) float g_h1  [NTOK * MLPH];
// split-K partials: [split][blk][c(0..15)=acc,16=m,17=l][tid]
__device__ __align__(256) float g_part[(size_t)NSPLIT * NBLK * 18 * 128];

// ---------------- f32x2 packed helpers ----------------
__device__ __forceinline__ ull pk2(float lo, float hi) {
    ull r; asm("mov.b64 %0, {%1, %2};" : "=l"(r) : "f"(lo), "f"(hi)); return r;
}
__device__ __forceinline__ void upk2(ull p, float& lo, float& hi) {
    asm("mov.b64 {%0, %1}, %2;" : "=f"(lo), "=f"(hi) : "l"(p));
}
__device__ __forceinline__ ull fma2(ull a, ull b, ull c) {
    ull d; asm("fma.rn.f32x2 %0, %1, %2, %3;" : "=l"(d) : "l"(a), "l"(b), "l"(c)); return d;
}
__device__ __forceinline__ ull mul2(ull a, ull b) {
    ull d; asm("mul.rn.f32x2 %0, %1, %2;" : "=l"(d) : "l"(a), "l"(b)); return d;
}

// ---------------- LayerNorm ----------------
__global__ void ln_kernel(const float* __restrict__ in,
                          const float* __restrict__ g,
                          const float* __restrict__ b,
                          float* __restrict__ out) {
    int t    = blockIdx.x * 8 + (threadIdx.x >> 5);
    int lane = threadIdx.x & 31;
    const float* row = in + (size_t)t * DIMC;
    float v0 = row[lane], v1 = row[lane + 32], v2 = row[lane + 64];
    float s  = v0 + v1 + v2;
    float sq = v0 * v0 + v1 * v1 + v2 * v2;
    #pragma unroll
    for (int o = 16; o; o >>= 1) {
        s  += __shfl_xor_sync(0xffffffffu, s,  o);
        sq += __shfl_xor_sync(0xffffffffu, sq, o);
    }
    float mean = s * (1.0f / DIMC);
    float var  = sq * (1.0f / DIMC) - mean * mean;
    float r    = rsqrtf(var + 1e-5f);
    float* orow = out + (size_t)t * DIMC;
    orow[lane]      = (v0 - mean) * r * g[lane]      + b[lane];
    orow[lane + 32] = (v1 - mean) * r * g[lane + 32] + b[lane + 32];
    orow[lane + 64] = (v2 - mean) * r * g[lane + 64] + b[lane + 64];
}

// ---------------- token GEMM (weights read via LDG.128) ----------------
template <int CIN, int COUT, int TM, int MODE>  // MODE: 0=+b, 1=+b+res, 2=gelu(+b)
__global__ void tok_gemm(const float* __restrict__ in,
                         const float* __restrict__ w,
                         const float* __restrict__ bias,
                         const float* __restrict__ res,
                         float* __restrict__ out) {
    __shared__ __align__(16) float xs[CIN * TM];   // [c][t]
    int t0 = blockIdx.x * TM;
    for (int i = threadIdx.x; i < TM * CIN; i += COUT) {
        int t = i / CIN, c = i - t * CIN;
        xs[c * TM + t] = in[(size_t)t0 * CIN + i];
    }
    __syncthreads();
    int o = threadIdx.x;
    float acc[TM];
    #pragma unroll
    for (int t = 0; t < TM; t++) acc[t] = 0.0f;
    const float4* w4 = (const float4*)(w + (size_t)o * CIN);
    #pragma unroll 2
    for (int c4 = 0; c4 < CIN / 4; c4++) {
        float4 wvec = w4[c4];
        #pragma unroll
        for (int u = 0; u < 4; u++) {
            float wv = (u == 0) ? wvec.x : (u == 1) ? wvec.y : (u == 2) ? wvec.z : wvec.w;
            const float4* xp = (const float4*)(xs + (4 * c4 + u) * TM);
            #pragma unroll
            for (int t4 = 0; t4 < TM / 4; t4++) {
                float4 a = xp[t4];
                acc[4 * t4 + 0] += a.x * wv;
                acc[4 * t4 + 1] += a.y * wv;
                acc[4 * t4 + 2] += a.z * wv;
                acc[4 * t4 + 3] += a.w * wv;
            }
        }
    }
    float bo = bias[o];
    #pragma unroll
    for (int t = 0; t < TM; t++) {
        float v = acc[t] + bo;
        if (MODE == 1) v += res[(size_t)(t0 + t) * COUT + o];
        if (MODE == 2) v = 0.5f * v * (1.0f + erff(v * 0.70710678118654752f));
        out[(size_t)(t0 + t) * COUT + o] = v;
    }
}

// ---------------- bias precompute ----------------
__global__ void bias_kernel(const int* __restrict__ rpi, const float* __restrict__ rpb) {
    int i = blockIdx.x * 256 + threadIdx.x;
    if (i >= KW3 * QW3) return;
    int k = i >> 9, q = i & 511;
    int idx = rpi[q * KW3 + k];
    #pragma unroll
    for (int h = 0; h < HEADS; h++)
        g_bias[((size_t)h * KW3 + k) * QW3 + q] = rpb[idx * HEADS + h];
}

// ---------------- attention (split-K over key tiles) ----------------
__global__ void __launch_bounds__(128) attn_kernel() {
    __shared__ float4 ks4[64 * 4];
    __shared__ float4 vs4[64 * 4];

    int b     = blockIdx.x;                      // 0..647
    int split = blockIdx.y;                      // 0..2
    int w   = b / 24;  int rem = b - w * 24;
    int h   = rem >> 2, qc = rem & 3;
    int wd  = w / 9;   int wr = w - wd * 9;
    int wh  = wr / 3;  int ww = wr - wh * 3;
    int tid = threadIdx.x;

    int qw = (qc << 7) + tid;
    int z  = qw >> 6, y = (qw >> 3) & 7, xx = qw & 7;
    int tq = ((wd * 8 + z) * DSP + (wh * 8 + y)) * DSP + (ww * 8 + xx);

    const float4* qp4 = (const float4*)(g_qkv + (size_t)tq * 288 + h * HD);
    ull qp[8];
    #pragma unroll
    for (int i = 0; i < 4; i++) {
        float4 v = qp4[i];
        qp[2 * i]     = pk2(v.x * 0.25f, v.y * 0.25f);
        qp[2 * i + 1] = pk2(v.z * 0.25f, v.w * 0.25f);
    }

    ull accp[8];
    #pragma unroll
    for (int c = 0; c < 8; c++) accp[c] = 0ull;
    float m = -3.0e38f, l = 0.0f;

    const float* brow = g_bias + ((size_t)h * KW3) * QW3 + qw;

    int j = tid & 63;
    int kt0 = split * 9;
    #pragma unroll 1
    for (int kt = kt0; kt < kt0 + 9; kt++) {
        __syncthreads();
        {
            int kk = kt * 64 + j;
            int kz = kk / 144; int r2 = kk - kz * 144;
            int ky = r2 / 12;  int kx = r2 - ky * 12;
            int gz = wd * 8 + kz - PADW, gy = wh * 8 + ky - PADW, gx = ww * 8 + kx - PADW;
            float4* dst = (tid < 64 ? ks4 : vs4) + j * 4;
            if ((unsigned)gz < 24u && (unsigned)gy < 24u && (unsigned)gx < 24u) {
                const float4* src = (const float4*)(g_qkv +
                    (size_t)((gz * DSP + gy) * DSP + gx) * 288 + (tid < 64 ? 96 : 192) + h * HD);
                dst[0] = src[0]; dst[1] = src[1]; dst[2] = src[2]; dst[3] = src[3];
            } else {
                float4 zz = make_float4(0.f, 0.f, 0.f, 0.f);
                dst[0] = zz; dst[1] = zz; dst[2] = zz; dst[3] = zz;
            }
        }
        __syncthreads();

        const float* bk = brow + (size_t)kt * 64 * QW3;
        #pragma unroll 1
        for (int chunk = 0; chunk < 4; chunk++) {
            float lg[16]; float cm = -3.0e38f;
            #pragma unroll
            for (int i = 0; i < 16; i++) {
                int jj = (chunk << 4) + i;
                const float4* kf = ks4 + jj * 4;
                float4 k0 = kf[0], k1 = kf[1], k2 = kf[2], k3 = kf[3];
                // two independent 4-deep chains
                ull sp0 = mul2(qp[0], pk2(k0.x, k0.y));
                ull sp1 = mul2(qp[4], pk2(k2.x, k2.y));
                sp0 = fma2(qp[1], pk2(k0.z, k0.w), sp0);
                sp1 = fma2(qp[5], pk2(k2.z, k2.w), sp1);
                sp0 = fma2(qp[2], pk2(k1.x, k1.y), sp0);
                sp1 = fma2(qp[6], pk2(k3.x, k3.y), sp1);
                sp0 = fma2(qp[3], pk2(k1.z, k1.w), sp0);
                sp1 = fma2(qp[7], pk2(k3.z, k3.w), sp1);
                float a0, a1, b0, b1;
                upk2(sp0, a0, a1); upk2(sp1, b0, b1);
                float s = (a0 + a1) + (b0 + b1) + __ldg(bk + (size_t)jj * QW3);
                lg[i] = s; cm = fmaxf(cm, s);
            }
            if (cm > m) {
                float f = __expf(m - cm);
                ull fp = pk2(f, f);
                l *= f;
                #pragma unroll
                for (int c = 0; c < 8; c++) accp[c] = mul2(accp[c], fp);
                m = cm;
            }
            #pragma unroll
            for (int i = 0; i < 16; i++) {
                float p = __expf(lg[i] - m); l += p;
                ull pp = pk2(p, p);
                const float4* vf = vs4 + ((chunk << 4) + i) * 4;
                float4 v0 = vf[0], v1 = vf[1], v2 = vf[2], v3 = vf[3];
                accp[0] = fma2(pp, pk2(v0.x, v0.y), accp[0]);
                accp[1] = fma2(pp, pk2(v0.z, v0.w), accp[1]);
                accp[2] = fma2(pp, pk2(v1.x, v1.y), accp[2]);
                accp[3] = fma2(pp, pk2(v1.z, v1.w), accp[3]);
                accp[4] = fma2(pp, pk2(v2.x, v2.y), accp[4]);
                accp[5] = fma2(pp, pk2(v2.z, v2.w), accp[5]);
                accp[6] = fma2(pp, pk2(v3.x, v3.y), accp[6]);
                accp[7] = fma2(pp, pk2(v3.z, v3.w), accp[7]);
            }
        }
    }

    // write partials [split][blk][c][tid]
    float* base = g_part + (((size_t)split * NBLK + b) * 18) * 128 + tid;
    #pragma unroll
    for (int c = 0; c < 8; c++) {
        float lo, hi; upk2(accp[c], lo, hi);
        base[(2 * c) * 128]     = lo;
        base[(2 * c + 1) * 128] = hi;
    }
    base[16 * 128] = m;
    base[17 * 128] = l;
}

// ---------------- split-K combine ----------------
__global__ void __launch_bounds__(128) combine_kernel() {
    int b   = blockIdx.x;
    int tid = threadIdx.x;
    int w   = b / 24;  int rem = b - w * 24;
    int h   = rem >> 2, qc = rem & 3;
    int wd  = w / 9;   int wr = w - wd * 9;
    int wh  = wr / 3;  int ww = wr - wh * 3;

    int qw = (qc << 7) + tid;
    int z  = qw >> 6, y = (qw >> 3) & 7, xx = qw & 7;
    int tq = ((wd * 8 + z) * DSP + (wh * 8 + y)) * DSP + (ww * 8 + xx);

    const float* p0 = g_part + (((size_t)0 * NBLK + b) * 18) * 128 + tid;
    const float* p1 = g_part + (((size_t)1 * NBLK + b) * 18) * 128 + tid;
    const float* p2 = g_part + (((size_t)2 * NBLK + b) * 18) * 128 + tid;

    float m0 = p0[16 * 128], m1 = p1[16 * 128], m2 = p2[16 * 128];
    float M  = fmaxf(m0, fmaxf(m1, m2));
    float f0 = __expf(m0 - M), f1 = __expf(m1 - M), f2 = __expf(m2 - M);
    float L  = p0[17 * 128] * f0 + p1[17 * 128] * f1 + p2[17 * 128] * f2;
    float inv = 1.0f / L;

    float* op = g_attn + (size_t)tq * DIMC + h * HD;
    #pragma unroll
    for (int c = 0; c < 16; c++) {
        float v = p0[c * 128] * f0 + p1[c * 128] * f1 + p2[c * 128] * f2;
        op[c] = v * inv;
    }
}

// ---------------- launch ----------------
extern "C" void kernel_launch(void* const* d_in, const int* in_sizes, int n_in,
                              void* d_out, int out_size) {
    const float* x      = (const float*)d_in[0];
    const float* ln1_w  = (const float*)d_in[1];
    const float* ln1_b  = (const float*)d_in[2];
    const float* qkv_w  = (const float*)d_in[3];
    const float* qkv_b  = (const float*)d_in[4];
    const float* rpb    = (const float*)d_in[5];
    const float* proj_w = (const float*)d_in[6];
    const float* proj_b = (const float*)d_in[7];
    const float* ln2_w  = (const float*)d_in[8];
    const float* ln2_b  = (const float*)d_in[9];
    const float* fc1_w  = (const float*)d_in[10];
    const float* fc1_b  = (const float*)d_in[11];
    const float* fc2_w  = (const float*)d_in[12];
    const float* fc2_b  = (const float*)d_in[13];
    const int*   rpi    = (const int*)  d_in[14];
    float* out = (float*)d_out;

    float* xn   = nullptr; cudaGetSymbolAddress((void**)&xn,   g_xn);
    float* qkv  = nullptr; cudaGetSymbolAddress((void**)&qkv,  g_qkv);
    float* attn = nullptr; cudaGetSymbolAddress((void**)&attn, g_attn);
    float* x2   = nullptr; cudaGetSymbolAddress((void**)&x2,   g_x2);
    float* x2n  = nullptr; cudaGetSymbolAddress((void**)&x2n,  g_x2n);
    float* h1   = nullptr; cudaGetSymbolAddress((void**)&h1,   g_h1);

    bias_kernel<<<(KW3 * QW3 + 255) / 256, 256>>>(rpi, rpb);

    ln_kernel<<<NTOK / 8, 256>>>(x, ln1_w, ln1_b, xn);
    tok_gemm<96, 288, 16, 0><<<NTOK / 16, 288>>>(xn, qkv_w, qkv_b, nullptr, qkv);

    attn_kernel<<<dim3(NBLK, NSPLIT), 128>>>();
    combine_kernel<<<NBLK, 128>>>();

    tok_gemm<96, 96, 8, 1><<<NTOK / 8, 96>>>(attn, proj_w, proj_b, x, x2);
    ln_kernel<<<NTOK / 8, 256>>>(x2, ln2_w, ln2_b, x2n);
    tok_gemm<96, 192, 16, 2><<<NTOK / 16, 192>>>(x2n, fc1_w, fc1_b, nullptr, h1);
    tok_gemm<192, 96, 8, 1><<<NTOK / 8, 96>>>(h1, fc2_w, fc2_b, x2, out);
}

// round 4
// speedup vs baseline: 2.2623x; 1.6298x over previous
#include <cuda_runtime.h>
#include <cuda_bf16.h>
#include <math.h>

// ---------------- problem constants ----------------
#define DIMC   96
#define HEADS  6
#define HD     16
#define PADW   2
#define DSP    24
#define NTOK   (24*24*24)
#define NWIN   27
#define QW3    512
#define KW3    1728
#define MLPH   192
#define NSPLIT 3
#define NBLK   (NWIN*HEADS*4)      // 648 (w,h,qc) blocks
#define KSPLIT 576                 // keys per split
#define NKT    18                  // 32-key tiles per split
#define LOG2E  1.44269504088896341f

// ---------------- scratch ----------------
__device__ __align__(256) float g_xn  [NTOK * DIMC];
__device__ __align__(256) float g_qkv [NTOK * 3 * DIMC];
__device__ __align__(256) float g_bias[(size_t)HEADS * QW3 * KW3];   // [h][q][k], pre-scaled by log2e
__device__ __align__(256) float g_attn[NTOK * DIMC];
__device__ __align__(256) float g_x2  [NTOK * DIMC];
__device__ __align__(256) float g_x2n [NTOK * DIMC];
__device__ __align__(256) float g_h1  [NTOK * MLPH];
// partials: [split][blk][q_local(128)][18]  (0..15 = O dims, 16 = m(log2), 17 = l)
__device__ __align__(256) float g_part[(size_t)NSPLIT * NBLK * 128 * 18];

// ---------------- small asm helpers ----------------
__device__ __forceinline__ unsigned bfpack(float lo, float hi) {
    unsigned d; asm("cvt.rn.bf16x2.f32 %0, %1, %2;" : "=r"(d) : "f"(hi), "f"(lo)); return d;
}
__device__ __forceinline__ float ex2(float x) {
    float y; asm("ex2.approx.f32 %0, %1;" : "=f"(y) : "f"(x)); return y;
}
__device__ __forceinline__ void mma16816(float* d, const unsigned* a, unsigned b0, unsigned b1) {
    asm volatile("mma.sync.aligned.m16n8k16.row.col.f32.bf16.bf16.f32 "
        "{%0,%1,%2,%3}, {%4,%5,%6,%7}, {%8,%9}, {%0,%1,%2,%3};"
        : "+f"(d[0]), "+f"(d[1]), "+f"(d[2]), "+f"(d[3])
        : "r"(a[0]), "r"(a[1]), "r"(a[2]), "r"(a[3]), "r"(b0), "r"(b1));
}

// ---------------- LayerNorm ----------------
__global__ void ln_kernel(const float* __restrict__ in,
                          const float* __restrict__ g,
                          const float* __restrict__ b,
                          float* __restrict__ out) {
    int t    = blockIdx.x * 8 + (threadIdx.x >> 5);
    int lane = threadIdx.x & 31;
    const float* row = in + (size_t)t * DIMC;
    float v0 = row[lane], v1 = row[lane + 32], v2 = row[lane + 64];
    float s  = v0 + v1 + v2;
    float sq = v0 * v0 + v1 * v1 + v2 * v2;
    #pragma unroll
    for (int o = 16; o; o >>= 1) {
        s  += __shfl_xor_sync(0xffffffffu, s,  o);
        sq += __shfl_xor_sync(0xffffffffu, sq, o);
    }
    float mean = s * (1.0f / DIMC);
    float var  = sq * (1.0f / DIMC) - mean * mean;
    float r    = rsqrtf(var + 1e-5f);
    float* orow = out + (size_t)t * DIMC;
    orow[lane]      = (v0 - mean) * r * g[lane]      + b[lane];
    orow[lane + 32] = (v1 - mean) * r * g[lane + 32] + b[lane + 32];
    orow[lane + 64] = (v2 - mean) * r * g[lane + 64] + b[lane + 64];
}

// ---------------- token GEMM ----------------
template <int CIN, int COUT, int TM, int MODE>  // MODE: 0=+b, 1=+b+res, 2=gelu(+b)
__global__ void tok_gemm(const float* __restrict__ in,
                         const float* __restrict__ w,
                         const float* __restrict__ bias,
                         const float* __restrict__ res,
                         float* __restrict__ out) {
    __shared__ __align__(16) float xs[CIN * TM];   // [c][t]
    int t0 = blockIdx.x * TM;
    for (int i = threadIdx.x; i < TM * CIN; i += COUT) {
        int t = i / CIN, c = i - t * CIN;
        xs[c * TM + t] = in[(size_t)t0 * CIN + i];
    }
    __syncthreads();
    int o = threadIdx.x;
    float acc[TM];
    #pragma unroll
    for (int t = 0; t < TM; t++) acc[t] = 0.0f;
    const float4* w4 = (const float4*)(w + (size_t)o * CIN);
    #pragma unroll 2
    for (int c4 = 0; c4 < CIN / 4; c4++) {
        float4 wvec = w4[c4];
        #pragma unroll
        for (int u = 0; u < 4; u++) {
            float wv = (u == 0) ? wvec.x : (u == 1) ? wvec.y : (u == 2) ? wvec.z : wvec.w;
            const float4* xp = (const float4*)(xs + (4 * c4 + u) * TM);
            #pragma unroll
            for (int t4 = 0; t4 < TM / 4; t4++) {
                float4 a = xp[t4];
                acc[4 * t4 + 0] += a.x * wv;
                acc[4 * t4 + 1] += a.y * wv;
                acc[4 * t4 + 2] += a.z * wv;
                acc[4 * t4 + 3] += a.w * wv;
            }
        }
    }
    float bo = bias[o];
    #pragma unroll
    for (int t = 0; t < TM; t++) {
        float v = acc[t] + bo;
        if (MODE == 1) v += res[(size_t)(t0 + t) * COUT + o];
        if (MODE == 2) v = 0.5f * v * (1.0f + erff(v * 0.70710678118654752f));
        out[(size_t)(t0 + t) * COUT + o] = v;
    }
}

// ---------------- bias precompute: g_bias[h][q][k] = rpb[rpi[q][k]][h] * log2e ----------------
__global__ void bias_kernel(const int* __restrict__ rpi, const float* __restrict__ rpb) {
    int i = blockIdx.x * 256 + threadIdx.x;       // i = q*1728 + k
    if (i >= QW3 * KW3) return;
    int idx = rpi[i];
    int q = i / KW3, k = i - q * KW3;
    #pragma unroll
    for (int h = 0; h < HEADS; h++)
        g_bias[((size_t)h * QW3 + q) * KW3 + k] = rpb[idx * HEADS + h] * LOG2E;
}

// ---------------- attention: mma.sync bf16, split-K, double-buffered fragment smem ----------------
__global__ void __launch_bounds__(128) attn_kernel() {
    // fragment-layout staging: K: [buf][nt(4)][lane(32)][rh(2)], V: [buf][kc(2)][nt(2)][lane][rh]
    __shared__ unsigned kf[2][4][32][2];
    __shared__ unsigned vf[2][2][2][32][2];

    int b     = blockIdx.x;                 // 0..647
    int split = blockIdx.y;                 // 0..2
    int w   = b / 24;  int rem = b - w * 24;
    int h   = rem >> 2, qc = rem & 3;
    int wd  = w / 9;   int wr = w - wd * 9;
    int wh  = wr / 3;  int ww = wr - wh * 3;
    int tid = threadIdx.x;
    int lane = tid & 31, wp = tid >> 5;
    int lj = lane & 3, lr = lane >> 2;

    int qbase = qc * 128 + wp * 32;

    // ---- Q fragments (bf16, scaled by 0.25*log2e) ----
    const float qs = 0.25f * LOG2E;
    unsigned qfrag[2][4];
    const float* bp[2][2];
    #pragma unroll
    for (int mt = 0; mt < 2; mt++) {
        #pragma unroll
        for (int half = 0; half < 2; half++) {
            int qw = qbase + mt * 16 + lr + 8 * half;
            int z = qw >> 6, y = (qw >> 3) & 7, xx = qw & 7;
            int tq = ((wd * 8 + z) * DSP + (wh * 8 + y)) * DSP + (ww * 8 + xx);
            const float* qp = g_qkv + (size_t)tq * 288 + h * HD + 2 * lj;
            float2 qa = *(const float2*)qp;
            float2 qb = *(const float2*)(qp + 8);
            qfrag[mt][half]     = bfpack(qa.x * qs, qa.y * qs);
            qfrag[mt][2 + half] = bfpack(qb.x * qs, qb.y * qs);
            bp[mt][half] = g_bias + ((size_t)(h * QW3) + qw) * KW3 + split * KSPLIT + 2 * lj;
        }
    }

    float O[2][2][4];
    float m[2][2], l[2][2];
    #pragma unroll
    for (int mt = 0; mt < 2; mt++)
        #pragma unroll
        for (int nt = 0; nt < 2; nt++)
            #pragma unroll
            for (int c = 0; c < 4; c++) O[mt][nt][c] = 0.0f;
    m[0][0] = m[0][1] = m[1][0] = m[1][1] = -1.0e30f;
    l[0][0] = l[0][1] = l[1][0] = l[1][1] = 0.0f;

    // ---- gather helpers (threads 0..31: K, 32..63: V) ----
    int gj = tid & 31;
    float4 stg[4];

    auto gload = [&](int tile) {
        if (tid < 64) {
            int kk = split * KSPLIT + tile * 32 + gj;
            int kz = kk / 144; int r2 = kk - kz * 144;
            int ky = r2 / 12;  int kx = r2 - ky * 12;
            int gz = wd * 8 + kz - PADW, gy = wh * 8 + ky - PADW, gx = ww * 8 + kx - PADW;
            if ((unsigned)gz < 24u && (unsigned)gy < 24u && (unsigned)gx < 24u) {
                const float4* src = (const float4*)(g_qkv +
                    (size_t)((gz * DSP + gy) * DSP + gx) * 288 + (tid < 32 ? 96 : 192) + h * HD);
                stg[0] = src[0]; stg[1] = src[1]; stg[2] = src[2]; stg[3] = src[3];
            } else {
                float4 zz = make_float4(0.f, 0.f, 0.f, 0.f);
                stg[0] = zz; stg[1] = zz; stg[2] = zz; stg[3] = zz;
            }
        }
    };
    auto gstore = [&](int buf) {
        const float* f = (const float*)stg;
        if (tid < 32) {                    // K: key gj, 8 bf16x2 stores
            int nt = gj >> 3, lgrp = 4 * (gj & 7);
            #pragma unroll
            for (int dp = 0; dp < 8; dp++)
                kf[buf][nt][lgrp + (dp & 3)][dp >> 2] = bfpack(f[2 * dp], f[2 * dp + 1]);
        } else if (tid < 64) {             // V: key gj, 16 bf16 half-stores
            int kc = gj >> 4, kk = gj & 15;
            int slotj = (kk >> 1) & 3, rh = kk >> 3, p = kk & 1;
            #pragma unroll
            for (int n = 0; n < 16; n++) {
                __nv_bfloat16* dst = (__nv_bfloat16*)&vf[buf][kc][n >> 3][4 * (n & 7) + slotj][rh];
                dst[p] = __float2bfloat16(f[n]);
            }
        }
    };

    gload(0);
    gstore(0);
    __syncthreads();

    #pragma unroll 1
    for (int t = 0; t < NKT; t++) {
        int buf = t & 1;
        if (t + 1 < NKT) gload(t + 1);

        // ---- S = bias; S += Q K^T ----
        float S[2][4][4];
        #pragma unroll
        for (int mt = 0; mt < 2; mt++)
            #pragma unroll
            for (int nt = 0; nt < 4; nt++) {
                float2 b0 = *(const float2*)(bp[mt][0] + t * 32 + nt * 8);
                float2 b1 = *(const float2*)(bp[mt][1] + t * 32 + nt * 8);
                S[mt][nt][0] = b0.x; S[mt][nt][1] = b0.y;
                S[mt][nt][2] = b1.x; S[mt][nt][3] = b1.y;
            }
        #pragma unroll
        for (int nt = 0; nt < 4; nt++) {
            unsigned kb0 = kf[buf][nt][lane][0], kb1 = kf[buf][nt][lane][1];
            mma16816(S[0][nt], qfrag[0], kb0, kb1);
            mma16816(S[1][nt], qfrag[1], kb0, kb1);
        }

        // ---- online softmax (exp2 domain) ----
        unsigned pfrag[2][2][4];
        #pragma unroll
        for (int mt = 0; mt < 2; mt++) {
            #pragma unroll
            for (int half = 0; half < 2; half++) {
                int c0 = 2 * half;
                float rm = fmaxf(S[mt][0][c0], S[mt][0][c0 + 1]);
                rm = fmaxf(rm, fmaxf(S[mt][1][c0], S[mt][1][c0 + 1]));
                rm = fmaxf(rm, fmaxf(S[mt][2][c0], S[mt][2][c0 + 1]));
                rm = fmaxf(rm, fmaxf(S[mt][3][c0], S[mt][3][c0 + 1]));
                rm = fmaxf(rm, __shfl_xor_sync(0xffffffffu, rm, 1));
                rm = fmaxf(rm, __shfl_xor_sync(0xffffffffu, rm, 2));
                float mo = m[mt][half];
                float mn = fmaxf(mo, rm);
                float sc = ex2(mo - mn);
                m[mt][half] = mn;
                O[mt][0][c0] *= sc; O[mt][0][c0 + 1] *= sc;
                O[mt][1][c0] *= sc; O[mt][1][c0 + 1] *= sc;
                float ls = 0.0f;
                #pragma unroll
                for (int nt = 0; nt < 4; nt++) {
                    float p0 = ex2(S[mt][nt][c0] - mn);
                    float p1 = ex2(S[mt][nt][c0 + 1] - mn);
                    ls += p0 + p1;
                    S[mt][nt][c0] = p0; S[mt][nt][c0 + 1] = p1;
                }
                // FIX (R3 bug): row sum lives across the 4 lj threads of the quad
                ls += __shfl_xor_sync(0xffffffffu, ls, 1);
                ls += __shfl_xor_sync(0xffffffffu, ls, 2);
                l[mt][half] = l[mt][half] * sc + ls;
            }
            #pragma unroll
            for (int kc = 0; kc < 2; kc++) {
                pfrag[mt][kc][0] = bfpack(S[mt][2 * kc][0],     S[mt][2 * kc][1]);
                pfrag[mt][kc][1] = bfpack(S[mt][2 * kc][2],     S[mt][2 * kc][3]);
                pfrag[mt][kc][2] = bfpack(S[mt][2 * kc + 1][0], S[mt][2 * kc + 1][1]);
                pfrag[mt][kc][3] = bfpack(S[mt][2 * kc + 1][2], S[mt][2 * kc + 1][3]);
            }
        }

        // ---- O += P V ----
        #pragma unroll
        for (int kc = 0; kc < 2; kc++)
            #pragma unroll
            for (int nt = 0; nt < 2; nt++) {
                unsigned vb0 = vf[buf][kc][nt][lane][0], vb1 = vf[buf][kc][nt][lane][1];
                mma16816(O[0][nt], pfrag[0][kc], vb0, vb1);
                mma16816(O[1][nt], pfrag[1][kc], vb0, vb1);
            }

        if (t + 1 < NKT) {
            __syncthreads();
            gstore(buf ^ 1);
            __syncthreads();
        }
    }

    // ---- write partials ----
    float* base = g_part + (((size_t)split * NBLK + b) * 128) * 18;
    #pragma unroll
    for (int mt = 0; mt < 2; mt++)
        #pragma unroll
        for (int half = 0; half < 2; half++) {
            int ql = wp * 32 + mt * 16 + lr + 8 * half;
            float* row = base + (size_t)ql * 18;
            int c0 = 2 * half;
            *(float2*)(row + 2 * lj)     = make_float2(O[mt][0][c0], O[mt][0][c0 + 1]);
            *(float2*)(row + 8 + 2 * lj) = make_float2(O[mt][1][c0], O[mt][1][c0 + 1]);
            if (lj == 0) { row[16] = m[mt][half]; row[17] = l[mt][half]; }
        }
}

// ---------------- split-K combine (exp2 domain) ----------------
__global__ void __launch_bounds__(128) combine_kernel() {
    int b   = blockIdx.x;
    int tid = threadIdx.x;
    int w   = b / 24;  int rem = b - w * 24;
    int h   = rem >> 2, qc = rem & 3;
    int wd  = w / 9;   int wr = w - wd * 9;
    int wh  = wr / 3;  int ww = wr - wh * 3;

    int qw = qc * 128 + tid;
    int z  = qw >> 6, y = (qw >> 3) & 7, xx = qw & 7;
    int tq = ((wd * 8 + z) * DSP + (wh * 8 + y)) * DSP + (ww * 8 + xx);

    const float* p0 = g_part + (((size_t)0 * NBLK + b) * 128 + tid) * 18;
    const float* p1 = g_part + (((size_t)1 * NBLK + b) * 128 + tid) * 18;
    const float* p2 = g_part + (((size_t)2 * NBLK + b) * 128 + tid) * 18;

    float m0 = p0[16], m1 = p1[16], m2 = p2[16];
    float M  = fmaxf(m0, fmaxf(m1, m2));
    float f0 = ex2(m0 - M), f1 = ex2(m1 - M), f2 = ex2(m2 - M);
    float L  = p0[17] * f0 + p1[17] * f1 + p2[17] * f2;
    float inv = 1.0f / L;

    float* op = g_attn + (size_t)tq * DIMC + h * HD;
    #pragma unroll
    for (int c = 0; c < 16; c++)
        op[c] = (p0[c] * f0 + p1[c] * f1 + p2[c] * f2) * inv;
}

// ---------------- launch ----------------
extern "C" void kernel_launch(void* const* d_in, const int* in_sizes, int n_in,
                              void* d_out, int out_size) {
    const float* x      = (const float*)d_in[0];
    const float* ln1_w  = (const float*)d_in[1];
    const float* ln1_b  = (const float*)d_in[2];
    const float* qkv_w  = (const float*)d_in[3];
    const float* qkv_b  = (const float*)d_in[4];
    const float* rpb    = (const float*)d_in[5];
    const float* proj_w = (const float*)d_in[6];
    const float* proj_b = (const float*)d_in[7];
    const float* ln2_w  = (const float*)d_in[8];
    const float* ln2_b  = (const float*)d_in[9];
    const float* fc1_w  = (const float*)d_in[10];
    const float* fc1_b  = (const float*)d_in[11];
    const float* fc2_w  = (const float*)d_in[12];
    const float* fc2_b  = (const float*)d_in[13];
    const int*   rpi    = (const int*)  d_in[14];
    float* out = (float*)d_out;

    float* xn   = nullptr; cudaGetSymbolAddress((void**)&xn,   g_xn);
    float* qkv  = nullptr; cudaGetSymbolAddress((void**)&qkv,  g_qkv);
    float* attn = nullptr; cudaGetSymbolAddress((void**)&attn, g_attn);
    float* x2   = nullptr; cudaGetSymbolAddress((void**)&x2,   g_x2);
    float* x2n  = nullptr; cudaGetSymbolAddress((void**)&x2n,  g_x2n);
    float* h1   = nullptr; cudaGetSymbolAddress((void**)&h1,   g_h1);

    bias_kernel<<<(QW3 * KW3 + 255) / 256, 256>>>(rpi, rpb);

    ln_kernel<<<NTOK / 8, 256>>>(x, ln1_w, ln1_b, xn);
    tok_gemm<96, 288, 32, 0><<<NTOK / 32, 288>>>(xn, qkv_w, qkv_b, nullptr, qkv);

    attn_kernel<<<dim3(NBLK, NSPLIT), 128>>>();
    combine_kernel<<<NBLK, 128>>>();

    tok_gemm<96, 96, 16, 1><<<NTOK / 16, 96>>>(attn, proj_w, proj_b, x, x2);
    ln_kernel<<<NTOK / 8, 256>>>(x2, ln2_w, ln2_b, x2n);
    tok_gemm<96, 192, 32, 2><<<NTOK / 32, 192>>>(x2n, fc1_w, fc1_b, nullptr, h1);
    tok_gemm<192, 96, 16, 1><<<NTOK / 16, 96>>>(h1, fc2_w, fc2_b, x2, out);
}

// round 5
// speedup vs baseline: 2.8431x; 1.2567x over previous
#include <cuda_runtime.h>
#include <cuda_bf16.h>
#include <math.h>

// ---------------- problem constants ----------------
#define DIMC   96
#define HEADS  6
#define HD     16
#define PADW   2
#define DSP    24
#define NTOK   (24*24*24)
#define NWIN   27
#define QW3    512
#define KW3    1728
#define MLPH   192
#define NSPLIT 3
#define NBLK2  (NWIN*HEADS*8)      // 1296 (w,h,64-query chunk) blocks
#define KSPLIT 576
#define NKT    18                  // 32-key tiles per split
#define NTILE  54                  // 32-key tiles per window
#define LOG2E  1.44269504088896341f

typedef unsigned long long ull;

// ---------------- scratch ----------------
__device__ __align__(256) float g_xn  [NTOK * DIMC];
__device__ __align__(256) float g_qkv [NTOK * 3 * DIMC];
__device__ __align__(256) float g_bias[(size_t)HEADS * QW3 * KW3];   // [h][q][k], pre-scaled log2e
__device__ __align__(256) float g_attn[NTOK * DIMC];
__device__ __align__(256) float g_x2  [NTOK * DIMC];
__device__ __align__(256) float g_x2n [NTOK * DIMC];
__device__ __align__(256) float g_h1  [NTOK * MLPH];
// K/V pre-gathered in mma fragment layout: [w][h][tile(54)][...256 u32 words...]
__device__ __align__(256) unsigned g_kf[(size_t)NWIN * HEADS * NTILE * 256];
__device__ __align__(256) unsigned g_vf[(size_t)NWIN * HEADS * NTILE * 256];
// partials: [split][blk2][q_local(64)][18]
__device__ __align__(256) float g_part[(size_t)NSPLIT * NBLK2 * 64 * 18];

// ---------------- asm helpers ----------------
__device__ __forceinline__ unsigned bfpack(float lo, float hi) {
    unsigned d; asm("cvt.rn.bf16x2.f32 %0, %1, %2;" : "=r"(d) : "f"(hi), "f"(lo)); return d;
}
__device__ __forceinline__ float ex2(float x) {
    float y; asm("ex2.approx.f32 %0, %1;" : "=f"(y) : "f"(x)); return y;
}
__device__ __forceinline__ void mma16816(float* d, const unsigned* a, unsigned b0, unsigned b1) {
    asm volatile("mma.sync.aligned.m16n8k16.row.col.f32.bf16.bf16.f32 "
        "{%0,%1,%2,%3}, {%4,%5,%6,%7}, {%8,%9}, {%0,%1,%2,%3};"
        : "+f"(d[0]), "+f"(d[1]), "+f"(d[2]), "+f"(d[3])
        : "r"(a[0]), "r"(a[1]), "r"(a[2]), "r"(a[3]), "r"(b0), "r"(b1));
}
__device__ __forceinline__ ull pk2(float lo, float hi) {
    ull r; asm("mov.b64 %0, {%1, %2};" : "=l"(r) : "f"(lo), "f"(hi)); return r;
}
__device__ __forceinline__ void upk2(ull p, float& lo, float& hi) {
    asm("mov.b64 {%0, %1}, %2;" : "=f"(lo), "=f"(hi) : "l"(p));
}
__device__ __forceinline__ ull fma2(ull a, ull b, ull c) {
    ull d; asm("fma.rn.f32x2 %0, %1, %2, %3;" : "=l"(d) : "l"(a), "l"(b), "l"(c)); return d;
}

// ---------------- LayerNorm ----------------
__global__ void ln_kernel(const float* __restrict__ in,
                          const float* __restrict__ g,
                          const float* __restrict__ b,
                          float* __restrict__ out) {
    int t    = blockIdx.x * 8 + (threadIdx.x >> 5);
    int lane = threadIdx.x & 31;
    const float* row = in + (size_t)t * DIMC;
    float v0 = row[lane], v1 = row[lane + 32], v2 = row[lane + 64];
    float s  = v0 + v1 + v2;
    float sq = v0 * v0 + v1 * v1 + v2 * v2;
    #pragma unroll
    for (int o = 16; o; o >>= 1) {
        s  += __shfl_xor_sync(0xffffffffu, s,  o);
        sq += __shfl_xor_sync(0xffffffffu, sq, o);
    }
    float mean = s * (1.0f / DIMC);
    float var  = sq * (1.0f / DIMC) - mean * mean;
    float r    = rsqrtf(var + 1e-5f);
    float* orow = out + (size_t)t * DIMC;
    orow[lane]      = (v0 - mean) * r * g[lane]      + b[lane];
    orow[lane + 32] = (v1 - mean) * r * g[lane + 32] + b[lane + 32];
    orow[lane + 64] = (v2 - mean) * r * g[lane + 64] + b[lane + 64];
}

// ---------------- token GEMM (f32x2 packed accumulators) ----------------
template <int CIN, int COUT, int TM, int MODE>  // MODE: 0=+b, 1=+b+res, 2=gelu(+b)
__global__ void tok_gemm(const float* __restrict__ in,
                         const float* __restrict__ w,
                         const float* __restrict__ bias,
                         const float* __restrict__ res,
                         float* __restrict__ out) {
    __shared__ __align__(16) float xs[CIN * TM];   // [c][t]
    int t0 = blockIdx.x * TM;
    for (int i = threadIdx.x; i < TM * CIN; i += COUT) {
        int t = i / CIN, c = i - t * CIN;
        xs[c * TM + t] = in[(size_t)t0 * CIN + i];
    }
    __syncthreads();
    int o = threadIdx.x;
    ull acc2[TM / 2];
    #pragma unroll
    for (int t = 0; t < TM / 2; t++) acc2[t] = 0ull;
    const float4* w4 = (const float4*)(w + (size_t)o * CIN);
    #pragma unroll 2
    for (int c4 = 0; c4 < CIN / 4; c4++) {
        float4 wvec = w4[c4];
        #pragma unroll
        for (int u = 0; u < 4; u++) {
            float wv = (u == 0) ? wvec.x : (u == 1) ? wvec.y : (u == 2) ? wvec.z : wvec.w;
            ull wp2 = pk2(wv, wv);
            const ull* xp = (const ull*)(xs + (4 * c4 + u) * TM);
            #pragma unroll
            for (int t2 = 0; t2 < TM / 2; t2++)
                acc2[t2] = fma2(wp2, xp[t2], acc2[t2]);
        }
    }
    float bo = bias[o];
    #pragma unroll
    for (int t2 = 0; t2 < TM / 2; t2++) {
        float v0, v1; upk2(acc2[t2], v0, v1);
        v0 += bo; v1 += bo;
        if (MODE == 1) {
            v0 += res[(size_t)(t0 + 2 * t2) * COUT + o];
            v1 += res[(size_t)(t0 + 2 * t2 + 1) * COUT + o];
        }
        if (MODE == 2) {
            v0 = 0.5f * v0 * (1.0f + erff(v0 * 0.70710678118654752f));
            v1 = 0.5f * v1 * (1.0f + erff(v1 * 0.70710678118654752f));
        }
        out[(size_t)(t0 + 2 * t2) * COUT + o]     = v0;
        out[(size_t)(t0 + 2 * t2 + 1) * COUT + o] = v1;
    }
}

// ---------------- bias precompute ----------------
__global__ void bias_kernel(const int* __restrict__ rpi, const float* __restrict__ rpb) {
    int i = blockIdx.x * 256 + threadIdx.x;       // i = q*1728 + k
    if (i >= QW3 * KW3) return;
    int idx = rpi[i];
    int q = i / KW3, k = i - q * KW3;
    #pragma unroll
    for (int h = 0; h < HEADS; h++)
        g_bias[((size_t)h * QW3 + q) * KW3 + k] = rpb[idx * HEADS + h] * LOG2E;
}

// ---------------- K/V pre-gather into fragment layout ----------------
// grid = 27*54, block = 384: tid<192 -> K (h=tid/32, j=tid%32), else V
__global__ void __launch_bounds__(384) kvprep_kernel() {
    int blk = blockIdx.x;
    int w = blk / NTILE, T = blk - w * NTILE;
    int wd = w / 9; int wr = w - wd * 9;
    int wh = wr / 3; int ww = wr - wh * 3;
    int tid = threadIdx.x;
    int isV = tid >= 192;
    int r = isV ? tid - 192 : tid;
    int j = r & 31, h = r >> 5;

    int kk = T * 32 + j;
    int kz = kk / 144; int r2 = kk - kz * 144;
    int ky = r2 / 12;  int kx = r2 - ky * 12;
    int gz = wd * 8 + kz - PADW, gy = wh * 8 + ky - PADW, gx = ww * 8 + kx - PADW;

    float f[16];
    if ((unsigned)gz < 24u && (unsigned)gy < 24u && (unsigned)gx < 24u) {
        const float4* src = (const float4*)(g_qkv +
            (size_t)((gz * DSP + gy) * DSP + gx) * 288 + (isV ? 192 : 96) + h * HD);
        ((float4*)f)[0] = src[0]; ((float4*)f)[1] = src[1];
        ((float4*)f)[2] = src[2]; ((float4*)f)[3] = src[3];
    } else {
        #pragma unroll
        for (int i = 0; i < 16; i++) f[i] = 0.0f;
    }

    size_t tilebase = ((size_t)(w * HEADS + h) * NTILE + T) * 256;
    if (!isV) {
        // K: same mapping as R4 smem gstore
        unsigned* dst = g_kf + tilebase;
        int nt = j >> 3, lgrp = 4 * (j & 7);
        #pragma unroll
        for (int dp = 0; dp < 8; dp++)
            dst[(nt * 32 + lgrp + (dp & 3)) * 2 + (dp >> 2)] = bfpack(f[2 * dp], f[2 * dp + 1]);
    } else {
        // V: pair keys (j even/odd) via shfl, each thread stores 8 packed words
        unsigned* dst = g_vf + tilebase;
        int kc = j >> 4, k2 = j & 15;
        int slotj = (k2 >> 1) & 3, rh = k2 >> 3;
        int nlo = (j & 1) * 8;
        #pragma unroll
        for (int n0 = 0; n0 < 8; n0++) {
            int n = nlo + n0;
            float fo = __shfl_xor_sync(0xffffffffu, f[n], 1);
            float ev = (j & 1) ? fo : f[n];
            float od = (j & 1) ? f[n] : fo;
            dst[((kc * 2 + (n >> 3)) * 32 + 4 * (n & 7) + slotj) * 2 + rh] = bfpack(ev, od);
        }
    }
}

// ---------------- attention: barrier-free, fragments streamed from gmem ----------------
__global__ void __launch_bounds__(128) attn_kernel() {
    int b     = blockIdx.x;                 // 0..1295
    int split = blockIdx.y;                 // 0..2
    int w   = b / 48;  int rem = b - w * 48;
    int h   = rem >> 3, qo = rem & 7;
    int wd  = w / 9;   int wr = w - wd * 9;
    int wh  = wr / 3;  int ww = wr - wh * 3;
    int tid = threadIdx.x;
    int lane = tid & 31, wp = tid >> 5;
    int lj = lane & 3, lr = lane >> 2;

    int qbase = qo * 64 + wp * 16;

    // ---- Q fragments (bf16, scaled 0.25*log2e) + bias row pointers ----
    const float qs = 0.25f * LOG2E;
    unsigned qfrag[4];
    const float* bp[2];
    #pragma unroll
    for (int half = 0; half < 2; half++) {
        int qw = qbase + 8 * half + lr;
        int z = qw >> 6, y = (qw >> 3) & 7, xx = qw & 7;
        int tq = ((wd * 8 + z) * DSP + (wh * 8 + y)) * DSP + (ww * 8 + xx);
        const float* qp = g_qkv + (size_t)tq * 288 + h * HD + 2 * lj;
        float2 qa = *(const float2*)qp;
        float2 qb = *(const float2*)(qp + 8);
        qfrag[half]     = bfpack(qa.x * qs, qa.y * qs);
        qfrag[2 + half] = bfpack(qb.x * qs, qb.y * qs);
        bp[half] = g_bias + ((size_t)(h * QW3) + qw) * KW3 + split * KSPLIT + 2 * lj;
    }

    // fragment streams (uint2 = one (b0,b1) pair per nt slot)
    const uint2* kG = (const uint2*)g_kf +
        ((size_t)(w * HEADS + h) * NTILE + split * NKT) * 128 + lane;
    const uint2* vG = (const uint2*)g_vf +
        ((size_t)(w * HEADS + h) * NTILE + split * NKT) * 128 + lane;

    float O[2][4];
    #pragma unroll
    for (int nt = 0; nt < 2; nt++)
        #pragma unroll
        for (int c = 0; c < 4; c++) O[nt][c] = 0.0f;
    float m[2] = { -1.0e30f, -1.0e30f };
    float l[2] = { 0.0f, 0.0f };

    uint2 kb[4], vb[4], kbn[4], vbn[4];
    #pragma unroll
    for (int nt = 0; nt < 4; nt++) { kb[nt] = kG[nt * 32]; vb[nt] = vG[nt * 32]; }

    #pragma unroll 1
    for (int t = 0; t < NKT; t++) {
        if (t + 1 < NKT) {
            const uint2* kN = kG + (t + 1) * 128;
            const uint2* vN = vG + (t + 1) * 128;
            #pragma unroll
            for (int nt = 0; nt < 4; nt++) { kbn[nt] = kN[nt * 32]; vbn[nt] = vN[nt * 32]; }
        }

        // ---- S = bias; S += Q K^T ----
        float S[4][4];
        #pragma unroll
        for (int nt = 0; nt < 4; nt++) {
            float2 b0 = *(const float2*)(bp[0] + t * 32 + nt * 8);
            float2 b1 = *(const float2*)(bp[1] + t * 32 + nt * 8);
            S[nt][0] = b0.x; S[nt][1] = b0.y;
            S[nt][2] = b1.x; S[nt][3] = b1.y;
        }
        #pragma unroll
        for (int nt = 0; nt < 4; nt++)
            mma16816(S[nt], qfrag, kb[nt].x, kb[nt].y);

        // ---- online softmax (exp2 domain) ----
        unsigned pfrag[2][4];
        #pragma unroll
        for (int half = 0; half < 2; half++) {
            int c0 = 2 * half;
            float rm = fmaxf(fmaxf(S[0][c0], S[0][c0 + 1]), fmaxf(S[1][c0], S[1][c0 + 1]));
            rm = fmaxf(rm, fmaxf(fmaxf(S[2][c0], S[2][c0 + 1]), fmaxf(S[3][c0], S[3][c0 + 1])));
            rm = fmaxf(rm, __shfl_xor_sync(0xffffffffu, rm, 1));
            rm = fmaxf(rm, __shfl_xor_sync(0xffffffffu, rm, 2));
            float mo = m[half];
            float mn = fmaxf(mo, rm);
            float sc = ex2(mo - mn);
            m[half] = mn;
            O[0][c0] *= sc; O[0][c0 + 1] *= sc;
            O[1][c0] *= sc; O[1][c0 + 1] *= sc;
            float ls = 0.0f;
            #pragma unroll
            for (int nt = 0; nt < 4; nt++) {
                float p0 = ex2(S[nt][c0] - mn);
                float p1 = ex2(S[nt][c0 + 1] - mn);
                ls += p0 + p1;
                S[nt][c0] = p0; S[nt][c0 + 1] = p1;
            }
            ls += __shfl_xor_sync(0xffffffffu, ls, 1);
            ls += __shfl_xor_sync(0xffffffffu, ls, 2);
            l[half] = l[half] * sc + ls;
        }
        #pragma unroll
        for (int kc = 0; kc < 2; kc++) {
            pfrag[kc][0] = bfpack(S[2 * kc][0],     S[2 * kc][1]);
            pfrag[kc][1] = bfpack(S[2 * kc][2],     S[2 * kc][3]);
            pfrag[kc][2] = bfpack(S[2 * kc + 1][0], S[2 * kc + 1][1]);
            pfrag[kc][3] = bfpack(S[2 * kc + 1][2], S[2 * kc + 1][3]);
        }

        // ---- O += P V ----
        #pragma unroll
        for (int kc = 0; kc < 2; kc++)
            #pragma unroll
            for (int nt = 0; nt < 2; nt++)
                mma16816(O[nt], pfrag[kc], vb[kc * 2 + nt].x, vb[kc * 2 + nt].y);

        #pragma unroll
        for (int nt = 0; nt < 4; nt++) { kb[nt] = kbn[nt]; vb[nt] = vbn[nt]; }
    }

    // ---- write partials ----
    float* base = g_part + (((size_t)split * NBLK2 + b) * 64) * 18;
    #pragma unroll
    for (int half = 0; half < 2; half++) {
        int ql = wp * 16 + 8 * half + lr;
        float* row = base + (size_t)ql * 18;
        int c0 = 2 * half;
        *(float2*)(row + 2 * lj)     = make_float2(O[0][c0], O[0][c0 + 1]);
        *(float2*)(row + 8 + 2 * lj) = make_float2(O[1][c0], O[1][c0 + 1]);
        if (lj == 0) { row[16] = m[half]; row[17] = l[half]; }
    }
}

// ---------------- split-K combine ----------------
__global__ void __launch_bounds__(64) combine_kernel() {
    int b   = blockIdx.x;                   // 0..1295
    int tid = threadIdx.x;                  // 0..63
    int w   = b / 48;  int rem = b - w * 48;
    int h   = rem >> 3, qo = rem & 7;
    int wd  = w / 9;   int wr = w - wd * 9;
    int wh  = wr / 3;  int ww = wr - wh * 3;

    int qw = qo * 64 + tid;
    int z  = qw >> 6, y = (qw >> 3) & 7, xx = qw & 7;
    int tq = ((wd * 8 + z) * DSP + (wh * 8 + y)) * DSP + (ww * 8 + xx);

    const float* p0 = g_part + (((size_t)0 * NBLK2 + b) * 64 + tid) * 18;
    const float* p1 = g_part + (((size_t)1 * NBLK2 + b) * 64 + tid) * 18;
    const float* p2 = g_part + (((size_t)2 * NBLK2 + b) * 64 + tid) * 18;

    float m0 = p0[16], m1 = p1[16], m2 = p2[16];
    float M  = fmaxf(m0, fmaxf(m1, m2));
    float f0 = ex2(m0 - M), f1 = ex2(m1 - M), f2 = ex2(m2 - M);
    float L  = p0[17] * f0 + p1[17] * f1 + p2[17] * f2;
    float inv = 1.0f / L;

    float* op = g_attn + (size_t)tq * DIMC + h * HD;
    #pragma unroll
    for (int c = 0; c < 16; c++)
        op[c] = (p0[c] * f0 + p1[c] * f1 + p2[c] * f2) * inv;
}

// ---------------- launch ----------------
extern "C" void kernel_launch(void* const* d_in, const int* in_sizes, int n_in,
                              void* d_out, int out_size) {
    const float* x      = (const float*)d_in[0];
    const float* ln1_w  = (const float*)d_in[1];
    const float* ln1_b  = (const float*)d_in[2];
    const float* qkv_w  = (const float*)d_in[3];
    const float* qkv_b  = (const float*)d_in[4];
    const float* rpb    = (const float*)d_in[5];
    const float* proj_w = (const float*)d_in[6];
    const float* proj_b = (const float*)d_in[7];
    const float* ln2_w  = (const float*)d_in[8];
    const float* ln2_b  = (const float*)d_in[9];
    const float* fc1_w  = (const float*)d_in[10];
    const float* fc1_b  = (const float*)d_in[11];
    const float* fc2_w  = (const float*)d_in[12];
    const float* fc2_b  = (const float*)d_in[13];
    const int*   rpi    = (const int*)  d_in[14];
    float* out = (float*)d_out;

    float* xn   = nullptr; cudaGetSymbolAddress((void**)&xn,   g_xn);
    float* qkv  = nullptr; cudaGetSymbolAddress((void**)&qkv,  g_qkv);
    float* attn = nullptr; cudaGetSymbolAddress((void**)&attn, g_attn);
    float* x2   = nullptr; cudaGetSymbolAddress((void**)&x2,   g_x2);
    float* x2n  = nullptr; cudaGetSymbolAddress((void**)&x2n,  g_x2n);
    float* h1   = nullptr; cudaGetSymbolAddress((void**)&h1,   g_h1);

    bias_kernel<<<(QW3 * KW3 + 255) / 256, 256>>>(rpi, rpb);

    ln_kernel<<<NTOK / 8, 256>>>(x, ln1_w, ln1_b, xn);
    tok_gemm<96, 288, 32, 0><<<NTOK / 32, 288>>>(xn, qkv_w, qkv_b, nullptr, qkv);

    kvprep_kernel<<<NWIN * NTILE, 384>>>();
    attn_kernel<<<dim3(NBLK2, NSPLIT), 128>>>();
    combine_kernel<<<NBLK2, 64>>>();

    tok_gemm<96, 96, 16, 1><<<NTOK / 16, 96>>>(attn, proj_w, proj_b, x, x2);
    ln_kernel<<<NTOK / 8, 256>>>(x2, ln2_w, ln2_b, x2n);
    tok_gemm<96, 192, 32, 2><<<NTOK / 32, 192>>>(x2n, fc1_w, fc1_b, nullptr, h1);
    tok_gemm<192, 96, 16, 1><<<NTOK / 16, 96>>>(h1, fc2_w, fc2_b, x2, out);
}